// round 1
// baseline (speedup 1.0000x reference)
#include <cuda_runtime.h>
#include <math.h>

#define ESL 4096
#define BATCH 64
#define EHS 256
#define NSPLIT 16
#define NWARPS 8
#define ROWS_PER_BLOCK (ESL / NSPLIT)          // 256
#define ROWS_PER_WARP (ROWS_PER_BLOCK / NWARPS) // 32

// split-softmax partials (no allocation allowed -> device globals)
__device__ float g_pc[NSPLIT * BATCH * EHS];   // partial context vectors
__device__ float g_pm[NSPLIT * BATCH];         // partial row-max
__device__ float g_pz[NSPLIT * BATCH];         // partial sum(exp)

__global__ __launch_bounds__(256)
void attn_pass1(const float* __restrict__ si,   // (1,64,256)
                const float* __restrict__ h,    // (4096,64,256)
                const float* __restrict__ W,    // (1,512)  [Wd | We]
                const float* __restrict__ bias) // (1,)
{
    const int split = blockIdx.x;
    const int b     = blockIdx.y;
    const int tid   = threadIdx.x;
    const int w     = tid >> 5;
    const int lane  = tid & 31;

    // --- per-lane slices of We (row dot) ---
    const float4* We4 = (const float4*)(W + EHS);  // W[:,256:512]
    const float4 we_a = We4[lane];
    const float4 we_b = We4[lane + 32];

    // --- d = dot(si_1[b], Wd) + bias, computed redundantly per warp (cheap) ---
    const float4* Wd4 = (const float4*)W;
    const float4* si4 = (const float4*)(si + (size_t)b * EHS);
    float4 sa = si4[lane], sb = si4[lane + 32];
    float4 wa = Wd4[lane], wb = Wd4[lane + 32];
    float d = sa.x*wa.x + sa.y*wa.y + sa.z*wa.z + sa.w*wa.w
            + sb.x*wb.x + sb.y*wb.y + sb.z*wb.z + sb.w*wb.w;
    #pragma unroll
    for (int o = 16; o; o >>= 1) d += __shfl_xor_sync(0xFFFFFFFFu, d, o);
    d += bias[0];

    // --- online softmax over this warp's rows ---
    float m = -INFINITY, Z = 0.0f;
    float4 acc_a = make_float4(0.f, 0.f, 0.f, 0.f);
    float4 acc_b = make_float4(0.f, 0.f, 0.f, 0.f);

    const int s_base = split * ROWS_PER_BLOCK + w;
    #pragma unroll 4
    for (int i = 0; i < ROWS_PER_WARP; i++) {
        const int s = s_base + i * NWARPS;
        const float4* hrow = (const float4*)(h + ((size_t)s * BATCH + b) * EHS);
        const float4 ha = hrow[lane];
        const float4 hb = hrow[lane + 32];

        float e = ha.x*we_a.x + ha.y*we_a.y + ha.z*we_a.z + ha.w*we_a.w
                + hb.x*we_b.x + hb.y*we_b.y + hb.z*we_b.z + hb.w*we_b.w;
        #pragma unroll
        for (int o = 16; o; o >>= 1) e += __shfl_xor_sync(0xFFFFFFFFu, e, o);

        const float en    = fmaxf(e + d, 0.0f);        // relu(e_dec + e_enc + b)
        const float m_new = fmaxf(m, en);
        const float scale = __expf(m - m_new);          // exp(-inf)=0 handles first iter
        const float p     = __expf(en - m_new);
        Z = Z * scale + p;
        acc_a.x = fmaf(acc_a.x, scale, p * ha.x);
        acc_a.y = fmaf(acc_a.y, scale, p * ha.y);
        acc_a.z = fmaf(acc_a.z, scale, p * ha.z);
        acc_a.w = fmaf(acc_a.w, scale, p * ha.w);
        acc_b.x = fmaf(acc_b.x, scale, p * hb.x);
        acc_b.y = fmaf(acc_b.y, scale, p * hb.y);
        acc_b.z = fmaf(acc_b.z, scale, p * hb.z);
        acc_b.w = fmaf(acc_b.w, scale, p * hb.w);
        m = m_new;
    }

    // --- combine 8 warp-partials -> 1 block partial ---
    __shared__ float4 s_c4[NWARPS][EHS / 4];   // 8 KB
    __shared__ float  s_m[NWARPS], s_z[NWARPS];
    s_c4[w][lane]      = acc_a;
    s_c4[w][lane + 32] = acc_b;
    if (lane == 0) { s_m[w] = m; s_z[w] = Z; }
    __syncthreads();

    float M = -INFINITY;
    #pragma unroll
    for (int p = 0; p < NWARPS; p++) M = fmaxf(M, s_m[p]);

    float Zt = 0.0f, c = 0.0f;
    const float* s_cf = (const float*)s_c4;
    #pragma unroll
    for (int p = 0; p < NWARPS; p++) {
        const float sc = __expf(s_m[p] - M);
        Zt += s_z[p] * sc;
        c  += s_cf[p * EHS + tid] * sc;
    }

    const int part = split * BATCH + b;
    g_pc[(size_t)part * EHS + tid] = c;
    if (tid == 0) { g_pm[part] = M; g_pz[part] = Zt; }
}

__global__ __launch_bounds__(256)
void attn_pass2(float* __restrict__ out)  // (1,64,256)
{
    const int b   = blockIdx.x;
    const int tid = threadIdx.x;

    float M = -INFINITY;
    #pragma unroll
    for (int p = 0; p < NSPLIT; p++) M = fmaxf(M, g_pm[p * BATCH + b]);

    float Zt = 0.0f, c = 0.0f;
    #pragma unroll
    for (int p = 0; p < NSPLIT; p++) {
        const int   part = p * BATCH + b;
        const float sc   = __expf(g_pm[part] - M);
        Zt += g_pz[part] * sc;
        c  += g_pc[(size_t)part * EHS + tid] * sc;
    }
    out[(size_t)b * EHS + tid] = c / Zt;
}

extern "C" void kernel_launch(void* const* d_in, const int* in_sizes, int n_in,
                              void* d_out, int out_size)
{
    const float* si   = (const float*)d_in[0];  // (1,64,256)
    const float* h    = (const float*)d_in[1];  // (4096,64,256)
    const float* W    = (const float*)d_in[2];  // (1,512)
    const float* bias = (const float*)d_in[3];  // (1,)
    float* out = (float*)d_out;                 // (1,64,256)

    dim3 grid1(NSPLIT, BATCH);
    attn_pass1<<<grid1, 256>>>(si, h, W, bias);
    attn_pass2<<<BATCH, 256>>>(out);
}